// round 10
// baseline (speedup 1.0000x reference)
#include <cuda_runtime.h>
#include <cuda_fp16.h>
#include <cstdint>
#include <math.h>

// Problem constants: B=64, T=512, K=512, H=512. M = B*T = 32768.
#define BB   64
#define TT   512
#define KK   512
#define HH   512
#define MM   (BB * TT)          // 32768

// ---------------------------------------------------------------------------
// Scratch (__device__ globals; no allocations allowed)
// ---------------------------------------------------------------------------
__device__ __half g_projh[3][(size_t)MM * HH];       // xz, xr, xh (fp16)
__device__ __half g_xs[(size_t)MM * KK];             // x in fp16
__device__ __half g_ws[3ull * HH * KK];              // W^T in fp16: [w][n][k]

// ---------------------------------------------------------------------------
// Helpers (sm_80-compatible PTX: ldmatrix / mma.sync / cp.async)
// ---------------------------------------------------------------------------
__device__ __forceinline__ uint32_t smem_u32(const void* p) {
    uint32_t a;
    asm("{ .reg .u64 t; cvta.to.shared.u64 t, %1; cvt.u32.u64 %0, t; }" : "=r"(a) : "l"(p));
    return a;
}

__device__ __forceinline__ void cpa16(uint32_t saddr, const void* g) {
    asm volatile("cp.async.cg.shared.global [%0], [%1], 16;" :: "r"(saddr), "l"(g));
}
#define CP_COMMIT() asm volatile("cp.async.commit_group;" ::: "memory")
template <int N>
__device__ __forceinline__ void cp_wait() {
    asm volatile("cp.async.wait_group %0;" :: "n"(N) : "memory");
}

__device__ __forceinline__ void ldsm_x4(uint32_t* r, uint32_t addr) {
    asm volatile("ldmatrix.sync.aligned.m8n8.x4.shared.b16 {%0,%1,%2,%3}, [%4];"
                 : "=r"(r[0]), "=r"(r[1]), "=r"(r[2]), "=r"(r[3]) : "r"(addr));
}
__device__ __forceinline__ void mma_f16(float* d, const uint32_t* a, const uint32_t* b) {
    asm volatile(
        "mma.sync.aligned.m16n8k16.row.col.f32.f16.f16.f32 "
        "{%0,%1,%2,%3}, {%4,%5,%6,%7}, {%8,%9}, {%0,%1,%2,%3};"
        : "+f"(d[0]), "+f"(d[1]), "+f"(d[2]), "+f"(d[3])
        : "r"(a[0]), "r"(a[1]), "r"(a[2]), "r"(a[3]), "r"(b[0]), "r"(b[1]));
}

// Single-MUFU tanh; sigmoid via exact identity s(x) = 0.5*tanh(x/2) + 0.5.
__device__ __forceinline__ float tanh_approx(float x) {
    float y;
    asm("tanh.approx.f32 %0, %1;" : "=f"(y) : "f"(x));
    return y;
}

// ---------------------------------------------------------------------------
// Convert x: linear fp32 -> fp16. 8 elements / thread.
// ---------------------------------------------------------------------------
__global__ void cvt_x_kernel(const float* __restrict__ x) {
    size_t i = ((size_t)blockIdx.x * blockDim.x + threadIdx.x) * 8;
    float4 v0 = *(const float4*)(x + i);
    float4 v1 = *(const float4*)(x + i + 4);
    __half2 h[4];
    h[0] = __floats2half2_rn(v0.x, v0.y);
    h[1] = __floats2half2_rn(v0.z, v0.w);
    h[2] = __floats2half2_rn(v1.x, v1.y);
    h[3] = __floats2half2_rn(v1.z, v1.w);
    *(uint4*)(g_xs + i) = *(uint4*)h;
}

// ---------------------------------------------------------------------------
// Convert weights with coalesced smem transpose: W[k][n] -> W^T[w][n][k] fp16.
// ---------------------------------------------------------------------------
__global__ void cvt_w_kernel(const float* __restrict__ kz,
                             const float* __restrict__ kr,
                             const float* __restrict__ kh) {
    __shared__ float tile[32][33];
    const int w  = blockIdx.z;
    const int k0 = blockIdx.x * 32;
    const int n0 = blockIdx.y * 32;
    const int tx = threadIdx.x, ty = threadIdx.y;
    const float* __restrict__ W = (w == 0) ? kz : (w == 1) ? kr : kh;

    #pragma unroll
    for (int r = 0; r < 4; r++)
        tile[ty + r * 8][tx] = W[(size_t)(k0 + ty + r * 8) * HH + n0 + tx];
    __syncthreads();

    #pragma unroll
    for (int r = 0; r < 4; r++) {
        int n = n0 + ty + r * 8;
        int k = k0 + tx;
        g_ws[((size_t)w * HH + n) * KK + k] = __float2half_rn(tile[tx][ty + r * 8]);
    }
}

// ---------------------------------------------------------------------------
// GEMM: g_projh[w] = fp16(A(32768 x 512) @ W_w), fp16 mma.sync, fp32 accum.
// Block 128x256x64 (was 128x128): 8 warps, 64x64 warp tiles -> smem LDSM
// bytes/MAC drops 1.5x (0.092 -> 0.061 B/MAC); shared port stops co-binding
// with the tensor pipe. 3-stage cp.async, 144KB smem, 1 CTA/SM.
// Smem rows 128B, swizzle chunk ^= row&7 (conflict-free ldmatrix).
// ---------------------------------------------------------------------------
#define GBM 128
#define GBN 256
#define GBK 64
#define NKT (KK / GBK)          // 8
#define GSTAGES 3
#define A_STG (GBM * GBK * 2)   // 16384 B
#define B_STG (GBN * GBK * 2)   // 32768 B
#define STG_BYTES (A_STG + B_STG)
#define GSMEM (GSTAGES * STG_BYTES)   // 147456 B

__global__ __launch_bounds__(256, 1)
void brc_mma_gemm(void) {
    extern __shared__ char smem[];
    const uint32_t sbase = smem_u32(smem);
    const int tid  = threadIdx.x;
    const int lane = tid & 31;
    const int wid  = tid >> 5;
    const int wm   = wid >> 2;          // 0..1  (m group, 64 rows)
    const int wn   = wid & 3;           // 0..3  (n group, 64 cols)

    const int w  = blockIdx.x >> 1;                 // weight select
    const int n0 = (blockIdx.x & 1) * GBN;          // n half
    const int m0 = blockIdx.y * GBM;

    const __half* __restrict__ Ap = g_xs;
    const __half* __restrict__ Bp = g_ws + (size_t)w * HH * KK;
    __half* __restrict__ C = g_projh[w];

    // A: 128 rows x 8 chunks = 1024 (4/thread); B: 256 rows x 8 = 2048 (8/thread)
    auto load_stage = [&](int kt, int s) {
        const uint32_t sa = sbase + s * STG_BYTES;
        const uint32_t sb = sa + A_STG;
        const size_t kb = (size_t)kt * GBK;
        #pragma unroll
        for (int q = 0; q < 4; q++) {
            int j = tid + q * 256;
            int row = j >> 3, c = j & 7;
            cpa16(sa + row * 128 + ((c ^ (row & 7)) * 16),
                  Ap + (size_t)(m0 + row) * KK + kb + c * 8);
        }
        #pragma unroll
        for (int q = 0; q < 8; q++) {
            int j = tid + q * 256;
            int row = j >> 3, c = j & 7;
            cpa16(sb + row * 128 + ((c ^ (row & 7)) * 16),
                  Bp + (size_t)(n0 + row) * KK + kb + c * 8);
        }
    };

    load_stage(0, 0); CP_COMMIT();
    load_stage(1, 1); CP_COMMIT();

    float acc[4][8][4];
    #pragma unroll
    for (int i = 0; i < 4; i++)
        #pragma unroll
        for (int j = 0; j < 8; j++)
            #pragma unroll
            for (int q = 0; q < 4; q++) acc[i][j][q] = 0.0f;

    // ldmatrix lane geometry (A path validated in R8; 8-wide-n B path in R9)
    const int a_r = lane & 15;
    const int a_c = lane >> 4;
    const int b_r = lane & 7;
    const int b_c = (lane >> 3) & 1;
    const int b_g = (lane >> 4) & 1;

    int sl = 0;                             // slot of k-tile kt (mod 3)
    for (int kt = 0; kt < NKT; kt++) {
        cp_wait<GSTAGES - 2>();
        __syncthreads();                    // all warps done reading slot of kt-1

        if (kt + 2 < NKT) {
            int ps = sl + 2; if (ps >= 3) ps -= 3;   // slot freed by kt-1
            load_stage(kt + 2, ps);
        }
        CP_COMMIT();

        const uint32_t sa = sbase + sl * STG_BYTES;
        const uint32_t sb = sa + A_STG;

        #pragma unroll
        for (int ks = 0; ks < 4; ks++) {
            uint32_t afr[4][4], bfr[8][2];
            #pragma unroll
            for (int mi = 0; mi < 4; mi++) {
                int row = wm * 64 + mi * 16 + a_r;
                int c   = ks * 2 + a_c;
                ldsm_x4(afr[mi], sa + row * 128 + ((c ^ (row & 7)) * 16));
            }
            #pragma unroll
            for (int np = 0; np < 4; np++) {
                int row = wn * 64 + (np * 2 + b_g) * 8 + b_r;
                int c   = ks * 2 + b_c;
                ldsm_x4(&bfr[np * 2][0], sb + row * 128 + ((c ^ (row & 7)) * 16));
            }
            #pragma unroll
            for (int mi = 0; mi < 4; mi++)
                #pragma unroll
                for (int ni = 0; ni < 8; ni++)
                    mma_f16(acc[mi][ni], afr[mi], bfr[ni]);
        }
        if (++sl == 3) sl = 0;
        // no trailing sync: top-of-loop sync covers slot-reuse hazard
    }

    // epilogue: fp16 store; thread holds cols (ec, ec+1) -> one half2 per row.
    const int er = lane >> 2;
    const int ec = (lane & 3) * 2;
    #pragma unroll
    for (int mi = 0; mi < 4; mi++) {
        #pragma unroll
        for (int ni = 0; ni < 8; ni++) {
            int gr = m0 + wm * 64 + mi * 16 + er;
            int gc = n0 + wn * 64 + ni * 8 + ec;
            __half2 v0 = __floats2half2_rn(acc[mi][ni][0], acc[mi][ni][1]);
            __half2 v1 = __floats2half2_rn(acc[mi][ni][2], acc[mi][ni][3]);
            *(__half2*)&C[(size_t)gr * HH + gc]       = v0;
            *(__half2*)&C[(size_t)(gr + 8) * HH + gc] = v1;
        }
    }
}

// ---------------------------------------------------------------------------
// Scan: ILP-1, 32K threads = 128 blocks x 256 threads (single wave; 8 warps
// per SM = 2/SMSP, double R8's warp density so stalls hide in the other
// warp). Distance-8 register LDG pipeline replaces the smem ring: 3 fp16
// loads/step, buffers fully unrolled so they live in registers.
// ---------------------------------------------------------------------------
#define SD 8

__global__ __launch_bounds__(256)
void brc_scan_kernel(const float* __restrict__ h0,
                     const float* __restrict__ mz,
                     const float* __restrict__ mr,
                     const float* __restrict__ bz,
                     const float* __restrict__ br,
                     float* __restrict__ out)
{
    const int idx = blockIdx.x * 256 + threadIdx.x;   // 0 .. 32767
    const int h = idx & 511;

    float hc        = h0[idx];
    const float vmz = mz[h];
    const float vmr = mr[h];
    const float vbz = bz[h];
    const float vbr = br[h];

    const __half* __restrict__ xz = g_projh[0];
    const __half* __restrict__ xr = g_projh[1];
    const __half* __restrict__ xh = g_projh[2];

    const size_t base = (size_t)(idx >> 9) * TT * HH + h;

    __half qz[SD], qr[SD], qh[SD];
    #pragma unroll
    for (int d = 0; d < SD; d++) {                    // prologue: t = 0..SD-1
        size_t off = base + (size_t)d * HH;
        qz[d] = xz[off];
        qr[d] = xr[off];
        qh[d] = xh[off];
    }

    for (int t = 0; t < TT; t += SD) {
        #pragma unroll
        for (int d = 0; d < SD; d++) {
            float az = __half2float(qz[d]) + vbz;
            float ar = __half2float(qr[d]) + vbr;
            float ah = __half2float(qh[d]);

            const int tn = t + d + SD;                // prefetch distance SD
            if (tn < TT) {
                size_t off = base + (size_t)tn * HH;
                qz[d] = xz[off];
                qr[d] = xr[off];
                qh[d] = xh[off];
            }

            float r  = tanh_approx(fmaf(hc, vmr, ar)) + 1.0f;
            float zg = fmaf(0.5f, tanh_approx(0.5f * fmaf(hc, vmz, az)), 0.5f);
            float cd = tanh_approx(fmaf(r, hc, ah));
            hc = fmaf(zg, hc - cd, cd);

            out[base + (size_t)(t + d) * HH] = hc;
        }
    }
}

// ---------------------------------------------------------------------------
// Launch. Inputs: x, h0, kz, kr, kh, mz, mr, bz, br. Output: [B, T, H] fp32.
// ---------------------------------------------------------------------------
extern "C" void kernel_launch(void* const* d_in, const int* in_sizes, int n_in,
                              void* d_out, int out_size)
{
    const float* x  = (const float*)d_in[0];
    const float* h0 = (const float*)d_in[1];
    const float* kz = (const float*)d_in[2];
    const float* kr = (const float*)d_in[3];
    const float* kh = (const float*)d_in[4];
    const float* mz = (const float*)d_in[5];
    const float* mr = (const float*)d_in[6];
    const float* bz = (const float*)d_in[7];
    const float* br = (const float*)d_in[8];
    float* out = (float*)d_out;

    cudaFuncSetAttribute(brc_mma_gemm, cudaFuncAttributeMaxDynamicSharedMemorySize,
                         GSMEM);

    cvt_x_kernel<<<(MM * KK / 8) / 256, 256>>>(x);
    cvt_w_kernel<<<dim3(16, 16, 3), dim3(32, 8)>>>(kz, kr, kh);

    dim3 ggrid(6, MM / GBM);           // (w, n-half) fast -> A m-block L2 reuse x6
    brc_mma_gemm<<<ggrid, 256, GSMEM>>>();

    brc_scan_kernel<<<128, 256>>>(h0, mz, mr, bz, br, out);
}